// round 11
// baseline (speedup 1.0000x reference)
#include <cuda_runtime.h>
#include <cuda_bf16.h>
#include <cstdint>

#define NN 2048
#define DIN 128
#define HH 256
#define DE 64
#define JSPLIT 8
#define JTILE 64
#define TILES 4              // (NN / JSPLIT) / JTILE
#define IBLK 64
#define NIBLK (NN / IBLK)    // 32

typedef unsigned long long u64;
typedef unsigned int u32;

__device__ float g_outx[NN * HH];
__device__ float g_sq[NN];
__device__ __align__(16) __nv_bfloat16 g_embh[NN * DE];
__device__ __align__(16) __nv_bfloat16 g_embl[NN * DE];
__device__ __align__(16) __nv_bfloat16 g_xlh[NN * DIN];
__device__ __align__(16) __nv_bfloat16 g_xll[NN * DIN];
__device__ float g_degp[JSPLIT * NN];
__device__ float g_accp[(size_t)JSPLIT * NN * DIN];
__device__ u32 g_cnt[NIBLK];        // zero-init; atomicInc wraps -> replay-safe

// ---- smem layout (bytes). pitches mod 128B == 16B -> ldmatrix conflict-free.
#define P1B 144u
#define P2B 272u
#define OF_EI_H 0u                    // 64 x P1B
#define OF_EI_L 9216u
#define OF_EJ_H 18432u                // 64 x P1B
#define OF_EJ_L 27648u
#define OF_XT_H 36864u                // 64 x P2B
#define OF_XT_L 54272u
#define OF_S_H  71680u                // 64 x P1B
#define OF_S_L  80896u
#define OF_SQJ  90112u                // 64 floats
#define OF_DEG  90368u                // 2 x 64 floats
#define OF_LAST 90880u                // 1 u32 (last-CTA flag)
#define ADJ_SMEM_BYTES 90896u

__device__ __forceinline__ u32 smem_u32(const void* p) {
    u32 a;
    asm("{ .reg .u64 t; cvta.to.shared.u64 t, %1; cvt.u32.u64 %0, t; }"
        : "=r"(a) : "l"(p));
    return a;
}
__device__ __forceinline__ void ldsm4(u32* r, u32 a) {
    asm volatile("ldmatrix.sync.aligned.m8n8.x4.shared.b16 {%0,%1,%2,%3}, [%4];"
        : "=r"(r[0]), "=r"(r[1]), "=r"(r[2]), "=r"(r[3]) : "r"(a));
}
__device__ __forceinline__ void ldsm4t(u32* r, u32 a) {
    asm volatile("ldmatrix.sync.aligned.m8n8.x4.trans.shared.b16 {%0,%1,%2,%3}, [%4];"
        : "=r"(r[0]), "=r"(r[1]), "=r"(r[2]), "=r"(r[3]) : "r"(a));
}
__device__ __forceinline__ void mma_bf16(float* c, const u32* a, u32 b0, u32 b1) {
    asm volatile(
        "mma.sync.aligned.m16n8k16.row.col.f32.bf16.bf16.f32 "
        "{%0,%1,%2,%3}, {%4,%5,%6,%7}, {%8,%9}, {%0,%1,%2,%3};"
        : "+f"(c[0]), "+f"(c[1]), "+f"(c[2]), "+f"(c[3])
        : "r"(a[0]), "r"(a[1]), "r"(a[2]), "r"(a[3]), "r"(b0), "r"(b1));
}
__device__ __forceinline__ float fast_rcp(float x) {
    float r = __uint_as_float(0x7EF311C3u - __float_as_uint(x));
    r = r * (2.0f - x * r);
    r = r * (2.0f - x * r);
    return r;
}
__device__ __forceinline__ void split_store(float2 v, char* smp, u32 off, u32 ldelta) {
    __nv_bfloat16 h0 = __float2bfloat16(v.x);
    __nv_bfloat16 h1 = __float2bfloat16(v.y);
    float l0 = v.x - __bfloat162float(h0);
    float l1 = v.y - __bfloat162float(h1);
    __nv_bfloat162 hp; hp.x = h0; hp.y = h1;
    __nv_bfloat162 lp; lp.x = __float2bfloat16(l0); lp.y = __float2bfloat16(l1);
    *(__nv_bfloat162*)(smp + off) = hp;
    *(__nv_bfloat162*)(smp + off + ldelta) = lp;
}
__device__ __forceinline__ void split_store_g(float v0, float v1,
                                              __nv_bfloat16* gh, __nv_bfloat16* gl) {
    __nv_bfloat16 h0 = __float2bfloat16(v0);
    __nv_bfloat16 h1 = __float2bfloat16(v1);
    float l0 = v0 - __bfloat162float(h0);
    float l1 = v1 - __bfloat162float(h1);
    __nv_bfloat162 hp; hp.x = h0; hp.y = h1;
    __nv_bfloat162 lp; lp.x = __float2bfloat16(l0); lp.y = __float2bfloat16(l1);
    *(__nv_bfloat162*)gh = hp;
    *(__nv_bfloat162*)gl = lp;
}

// ---------------------------------------------------------------------------
// Merged prologue GEMM on x:
//   blocks 0..3 -> out_x = relu(x@W0+b0) fp32 [2048,256]
//   blocks 4..5 -> x_last = x@W2+b2 -> bf16 hi/lo planes xlh/xll [2048,128]
// ---------------------------------------------------------------------------
__global__ void gemm01_kernel(const float* __restrict__ A,
                              const float* __restrict__ W0,
                              const float* __restrict__ b0,
                              float* __restrict__ outx,
                              const float* __restrict__ W2,
                              const float* __restrict__ b2,
                              __nv_bfloat16* __restrict__ xlh,
                              __nv_bfloat16* __restrict__ xll) {
    __shared__ float As[16][64];
    __shared__ float Bs[16][65];
    const bool second = blockIdx.x >= 4;
    const float* B = second ? W2 : W0;
    const float* bias = second ? b2 : b0;
    const int N = second ? DIN : HH;
    const int nbase = (second ? (blockIdx.x - 4) : blockIdx.x) * 64;

    int tid = threadIdx.x;
    int tx = tid & 15, ty = tid >> 4;
    int mbase = blockIdx.y * 64;

    float acc[4][4];
#pragma unroll
    for (int i = 0; i < 4; i++)
#pragma unroll
        for (int j = 0; j < 4; j++) acc[i][j] = 0.f;

#pragma unroll
    for (int k0 = 0; k0 < DIN; k0 += 16) {
        {
            int m = tid >> 2;
            int k = (tid & 3) << 2;
            float4 av = *reinterpret_cast<const float4*>(
                A + (size_t)(mbase + m) * DIN + k0 + k);
            As[k + 0][m] = av.x; As[k + 1][m] = av.y;
            As[k + 2][m] = av.z; As[k + 3][m] = av.w;
        }
#pragma unroll
        for (int r = 0; r < 4; r++) {
            int idx = tid + r * 256;
            int kk = idx >> 6, n = idx & 63;
            Bs[kk][n] = B[(size_t)(k0 + kk) * N + nbase + n];
        }
        __syncthreads();
#pragma unroll
        for (int kk = 0; kk < 16; kk++) {
            float a[4], b[4];
#pragma unroll
            for (int i = 0; i < 4; i++) a[i] = As[kk][ty * 4 + i];
#pragma unroll
            for (int j = 0; j < 4; j++) b[j] = Bs[kk][tx * 4 + j];
#pragma unroll
            for (int i = 0; i < 4; i++)
#pragma unroll
                for (int j = 0; j < 4; j++) acc[i][j] += a[i] * b[j];
        }
        __syncthreads();
    }
#pragma unroll
    for (int i = 0; i < 4; i++) {
        int row = mbase + ty * 4 + i;
        if (!second) {
#pragma unroll
            for (int j = 0; j < 4; j++) {
                int col = nbase + tx * 4 + j;
                float v = acc[i][j] + bias[col];
                outx[(size_t)row * HH + col] = v > 0.f ? v : 0.f;
            }
        } else {
            int col = nbase + tx * 4;
            float v[4];
#pragma unroll
            for (int j = 0; j < 4; j++) v[j] = acc[i][j] + bias[col + j];
            split_store_g(v[0], v[1], &xlh[(size_t)row * DIN + col],
                          &xll[(size_t)row * DIN + col]);
            split_store_g(v[2], v[3], &xlh[(size_t)row * DIN + col + 2],
                          &xll[(size_t)row * DIN + col + 2]);
        }
    }
}

// ---------------------------------------------------------------------------
// emb GEMM: emb = relu(out_x @ W1 + b1) -> bf16 hi/lo planes + fused row-sq.
// BM=32 (grid 64 CTAs) for latency hiding; thread tile 2x4.
// ---------------------------------------------------------------------------
__global__ void gemm_emb_kernel(const float* __restrict__ A,
                                const float* __restrict__ B,
                                const float* __restrict__ bias,
                                __nv_bfloat16* __restrict__ embh,
                                __nv_bfloat16* __restrict__ embl,
                                float* __restrict__ sqout) {
    __shared__ float As[16][33];
    __shared__ float Bs[16][65];
    const int N = DE, K = HH;
    int tid = threadIdx.x;
    int tx = tid & 15, ty = tid >> 4;
    int mbase = blockIdx.y * 32;

    float acc[2][4];
#pragma unroll
    for (int i = 0; i < 2; i++)
#pragma unroll
        for (int j = 0; j < 4; j++) acc[i][j] = 0.f;

#pragma unroll 4
    for (int k0 = 0; k0 < K; k0 += 16) {
        {
            int m = tid >> 3;
            int k = (tid & 7) << 1;
            float2 av = *reinterpret_cast<const float2*>(
                A + (size_t)(mbase + m) * K + k0 + k);
            As[k + 0][m] = av.x; As[k + 1][m] = av.y;
        }
#pragma unroll
        for (int r = 0; r < 4; r++) {
            int idx = tid + r * 256;
            int kk = idx >> 6, n = idx & 63;
            Bs[kk][n] = B[(size_t)(k0 + kk) * N + n];
        }
        __syncthreads();
#pragma unroll
        for (int kk = 0; kk < 16; kk++) {
            float a[2], b[4];
#pragma unroll
            for (int i = 0; i < 2; i++) a[i] = As[kk][ty * 2 + i];
#pragma unroll
            for (int j = 0; j < 4; j++) b[j] = Bs[kk][tx * 4 + j];
#pragma unroll
            for (int i = 0; i < 2; i++)
#pragma unroll
                for (int j = 0; j < 4; j++) acc[i][j] += a[i] * b[j];
        }
        __syncthreads();
    }

    float rowsq[2] = {0.f, 0.f};
#pragma unroll
    for (int i = 0; i < 2; i++) {
        int row = mbase + ty * 2 + i;
        int col = tx * 4;
        float v[4];
#pragma unroll
        for (int j = 0; j < 4; j++) {
            float u = acc[i][j] + bias[col + j];
            u = u > 0.f ? u : 0.f;
            v[j] = u;
            rowsq[i] += u * u;
        }
        split_store_g(v[0], v[1], &embh[(size_t)row * DE + col],
                      &embl[(size_t)row * DE + col]);
        split_store_g(v[2], v[3], &embh[(size_t)row * DE + col + 2],
                      &embl[(size_t)row * DE + col + 2]);
    }
    __shared__ float sqred[32][17];
#pragma unroll
    for (int i = 0; i < 2; i++) sqred[ty * 2 + i][tx] = rowsq[i];
    __syncthreads();
    if (tid < 32) {
        float s = 0.f;
#pragma unroll
        for (int j = 0; j < 16; j++) s += sqred[tid][j];
        sqout[mbase + tid] = s;
    }
}

// ---------------------------------------------------------------------------
// Warp-MMA fused adjacency kernel (bf16-split, 3-MMA compensation) with
// fused last-CTA final reduction (out = relu((sum_k acc)/(sum_k deg))).
// CTA = 64 i-rows x one j-split (4 tiles of 64 j). 256 threads (8 warps).
// ---------------------------------------------------------------------------
__global__ __launch_bounds__(256, 2)
void adj_mma_kernel(const __nv_bfloat16* __restrict__ embh,
                    const __nv_bfloat16* __restrict__ embl,
                    const float* __restrict__ sq,
                    const __nv_bfloat16* __restrict__ xlh,
                    const __nv_bfloat16* __restrict__ xll,
                    const float* __restrict__ temp_p,
                    const float* __restrict__ theta_p,
                    float* __restrict__ adj_out,
                    float* __restrict__ degp, float* __restrict__ accp,
                    float* __restrict__ out, u32* __restrict__ cnt) {
    extern __shared__ char sm[];
    const u32 sb = smem_u32(sm);
    float* sqjc  = (float*)(sm + OF_SQJ);
    float* degsm = (float*)(sm + OF_DEG);
    u32* lastf   = (u32*)(sm + OF_LAST);

    const int t = threadIdx.x;
    const int wm = t >> 5;
    const int lane = t & 31;
    const int wg = wm >> 2;
    const int wr = wm & 3;
    const int i0 = blockIdx.x * IBLK;
    const int jsp = blockIdx.y;
    const int jbase = jsp * (TILES * JTILE);
    const float cA = 1.0f + *temp_p;
    const float cB = 5.0f + *theta_p;
    const float c2A = 2.0f * cA;

    // ---- stage EI planes ----
    {
        const uint4* sH = (const uint4*)embh + (size_t)i0 * 8;
        const uint4* sL = (const uint4*)embl + (size_t)i0 * 8;
        for (int idx = t; idx < 512; idx += 256) {
            int row = idx >> 3, q = idx & 7;
            *(uint4*)(sm + OF_EI_H + row * P1B + q * 16) = sH[row * 8 + q];
            *(uint4*)(sm + OF_EI_L + row * P1B + q * 16) = sL[row * 8 + q];
        }
    }
    __syncthreads();

    // ---- A fragments (tile-invariant, hoisted) ----
    u32 ah[4][4], al[4][4];
    {
        const u32 abase = sb + OF_EI_H + (wr * 16 + (lane & 15)) * P1B + (lane >> 4) * 16;
#pragma unroll
        for (int ks = 0; ks < 4; ks++) {
            ldsm4(ah[ks], abase + ks * 32);
            ldsm4(al[ks], abase + (OF_EI_L - OF_EI_H) + ks * 32);
        }
    }

    const int ra = wr * 16 + (lane >> 2);
    const int rb = ra + 8;
    const float cbi_a = cB - cA * sq[i0 + ra];
    const float cbi_b = cB - cA * sq[i0 + rb];

    float acc2[8][4];
#pragma unroll
    for (int n = 0; n < 8; n++)
#pragma unroll
        for (int q = 0; q < 4; q++) acc2[n][q] = 0.f;
    float dega = 0.f, degb = 0.f;

    for (int tt = 0; tt < TILES; ++tt) {
        const int jb = jbase + tt * JTILE;
        if (tt > 0) __syncthreads();

        {
            const uint4* sH = (const uint4*)embh + (size_t)jb * 8;
            const uint4* sL = (const uint4*)embl + (size_t)jb * 8;
            for (int idx = t; idx < 512; idx += 256) {
                int row = idx >> 3, q = idx & 7;
                *(uint4*)(sm + OF_EJ_H + row * P1B + q * 16) = sH[row * 8 + q];
                *(uint4*)(sm + OF_EJ_L + row * P1B + q * 16) = sL[row * 8 + q];
            }
        }
        {
            const uint4* sH = (const uint4*)xlh + (size_t)jb * 16;
            const uint4* sL = (const uint4*)xll + (size_t)jb * 16;
            for (int idx = t; idx < 1024; idx += 256) {
                int row = idx >> 4, q = idx & 15;
                *(uint4*)(sm + OF_XT_H + row * P2B + q * 16) = sH[row * 16 + q];
                *(uint4*)(sm + OF_XT_L + row * P2B + q * 16) = sL[row * 16 + q];
            }
        }
        if (t < JTILE) sqjc[t] = cA * sq[jb + t];
        __syncthreads();

        // ---- phase 1: dot = embi @ embj^T ----
        float acc1[4][4];
#pragma unroll
        for (int n = 0; n < 4; n++)
#pragma unroll
            for (int q = 0; q < 4; q++) acc1[n][q] = 0.f;

        const u32 bjbase = sb + OF_EJ_H
                           + (wg * 32 + (lane & 7) + (lane >> 4) * 8) * P1B
                           + ((lane >> 3) & 1) * 16;
#pragma unroll
        for (int np = 0; np < 2; np++) {
#pragma unroll
            for (int ks = 0; ks < 4; ks++) {
                u32 bh[4], bl[4];
                u32 ba = bjbase + np * 16 * P1B + ks * 32;
                ldsm4(bh, ba);
                ldsm4(bl, ba + (OF_EJ_L - OF_EJ_H));
                mma_bf16(acc1[np * 2],     ah[ks], bh[0], bh[1]);
                mma_bf16(acc1[np * 2],     ah[ks], bl[0], bl[1]);
                mma_bf16(acc1[np * 2],     al[ks], bh[0], bh[1]);
                mma_bf16(acc1[np * 2 + 1], ah[ks], bh[2], bh[3]);
                mma_bf16(acc1[np * 2 + 1], ah[ks], bl[2], bl[3]);
                mma_bf16(acc1[np * 2 + 1], al[ks], bh[2], bh[3]);
            }
        }

        // ---- epilogue: sigmoid + eye, adj STG, deg, S split -> smem ----
#pragma unroll
        for (int nt = 0; nt < 4; nt++) {
            int jc = wg * 32 + nt * 8 + 2 * (lane & 3);
            float sj0 = sqjc[jc], sj1 = sqjc[jc + 1];
            float z00 = fmaf(c2A, acc1[nt][0], cbi_a - sj0);
            float z01 = fmaf(c2A, acc1[nt][1], cbi_a - sj1);
            float z10 = fmaf(c2A, acc1[nt][2], cbi_b - sj0);
            float z11 = fmaf(c2A, acc1[nt][3], cbi_b - sj1);
            float p00 = fast_rcp(1.f + __expf(-z00));
            float p01 = fast_rcp(1.f + __expf(-z01));
            float p10 = fast_rcp(1.f + __expf(-z10));
            float p11 = fast_rcp(1.f + __expf(-z11));
            if (i0 + ra == jb + jc)     p00 += 1.f;
            if (i0 + ra == jb + jc + 1) p01 += 1.f;
            if (i0 + rb == jb + jc)     p10 += 1.f;
            if (i0 + rb == jb + jc + 1) p11 += 1.f;
            dega += p00 + p01;
            degb += p10 + p11;
            *(float2*)&adj_out[(size_t)(i0 + ra) * NN + jb + jc] = make_float2(p00, p01);
            *(float2*)&adj_out[(size_t)(i0 + rb) * NN + jb + jc] = make_float2(p10, p11);
            split_store(make_float2(p00, p01), sm + OF_S_H,
                        ra * P1B + jc * 2, OF_S_L - OF_S_H);
            split_store(make_float2(p10, p11), sm + OF_S_H,
                        rb * P1B + jc * 2, OF_S_L - OF_S_H);
        }
        __syncthreads();

        // ---- phase 2: acc2 += S @ XT^T ----
        const u32 sbase = sb + OF_S_H + (wr * 16 + (lane & 15)) * P1B + (lane >> 4) * 16;
        const u32 btbase = sb + OF_XT_H
                           + ((lane & 7) + ((lane >> 3) & 1) * 8) * P2B
                           + wg * 128 + (lane >> 4) * 16;
#pragma unroll
        for (int ks = 0; ks < 4; ks++) {
            u32 sh[4], sl[4];
            ldsm4(sh, sbase + ks * 32);
            ldsm4(sl, sbase + (OF_S_L - OF_S_H) + ks * 32);
#pragma unroll
            for (int ndp = 0; ndp < 4; ndp++) {
                u32 bh[4], bl[4];
                u32 ba = btbase + ks * 16 * P2B + ndp * 32;
                ldsm4t(bh, ba);
                ldsm4t(bl, ba + (OF_XT_L - OF_XT_H));
                mma_bf16(acc2[ndp * 2],     sh, bh[0], bh[1]);
                mma_bf16(acc2[ndp * 2],     sh, bl[0], bl[1]);
                mma_bf16(acc2[ndp * 2],     sl, bh[0], bh[1]);
                mma_bf16(acc2[ndp * 2 + 1], sh, bh[2], bh[3]);
                mma_bf16(acc2[ndp * 2 + 1], sh, bl[2], bl[3]);
                mma_bf16(acc2[ndp * 2 + 1], sl, bh[2], bh[3]);
            }
        }
    }

    // ---- deg reduction into degp ----
    dega += __shfl_xor_sync(0xffffffffu, dega, 1);
    dega += __shfl_xor_sync(0xffffffffu, dega, 2);
    degb += __shfl_xor_sync(0xffffffffu, degb, 1);
    degb += __shfl_xor_sync(0xffffffffu, degb, 2);
    if ((lane & 3) == 0) {
        degsm[wg * IBLK + ra] = dega;
        degsm[wg * IBLK + rb] = degb;
    }
    __syncthreads();
    if (t < IBLK)
        degp[jsp * NN + i0 + t] = degsm[t] + degsm[IBLK + t];

    // ---- write acc2 partials ----
    float* ap = accp + ((size_t)jsp * NN + i0) * DIN;
#pragma unroll
    for (int nt = 0; nt < 8; nt++) {
        int dc = wg * 64 + nt * 8 + 2 * (lane & 3);
        *(float2*)&ap[(size_t)ra * DIN + dc] = make_float2(acc2[nt][0], acc2[nt][1]);
        *(float2*)&ap[(size_t)rb * DIN + dc] = make_float2(acc2[nt][2], acc2[nt][3]);
    }

    // ---- last-CTA fused final reduction for this i-block ----
    __syncthreads();              // all stores issued
    __threadfence();              // visible device-wide
    if (t == 0)
        *lastf = (atomicInc(&cnt[blockIdx.x], JSPLIT - 1) == JSPLIT - 1) ? 1u : 0u;
    __syncthreads();
    if (*lastf) {
        __threadfence();          // acquire others' partials
        const int row = t >> 2;               // 0..63
        const int grow = i0 + row;
        const int qb = (t & 3) * 8;           // float4 offset within row
        float d = 0.f;
#pragma unroll
        for (int k = 0; k < JSPLIT; k++) d += degp[k * NN + grow];
        const float dinv = 1.0f / d;
        const float4* apv = (const float4*)accp;
        const size_t rbase = (size_t)grow * (DIN / 4);
#pragma unroll
        for (int q = 0; q < 8; q++) {
            const size_t idx4 = rbase + qb + q;
            float4 a = apv[idx4];
#pragma unroll
            for (int k = 1; k < JSPLIT; k++) {
                float4 b = apv[(size_t)k * (NN * DIN / 4) + idx4];
                a.x += b.x; a.y += b.y; a.z += b.z; a.w += b.w;
            }
            float4 v;
            v.x = a.x * dinv; v.y = a.y * dinv; v.z = a.z * dinv; v.w = a.w * dinv;
            v.x = v.x > 0.f ? v.x : 0.f;  v.y = v.y > 0.f ? v.y : 0.f;
            v.z = v.z > 0.f ? v.z : 0.f;  v.w = v.w > 0.f ? v.w : 0.f;
            ((float4*)out)[idx4] = v;
        }
    }
}

extern "C" void kernel_launch(void* const* d_in, const int* in_sizes, int n_in,
                              void* d_out, int out_size) {
    const float* x     = (const float*)d_in[0];
    const float* W0    = (const float*)d_in[2];
    const float* b0    = (const float*)d_in[3];
    const float* W1    = (const float*)d_in[4];
    const float* b1    = (const float*)d_in[5];
    const float* W2    = (const float*)d_in[6];
    const float* b2    = (const float*)d_in[7];
    const float* temp  = (const float*)d_in[8];
    const float* theta = (const float*)d_in[9];

    float* out = (float*)d_out;                 // [NN, DIN] first
    float* adj_out = out + (size_t)NN * DIN;    // then [NN*NN] adjacency

    float *outx, *sq, *degp, *accp;
    __nv_bfloat16 *embh, *embl, *xlh, *xll;
    u32* cnt;
    cudaGetSymbolAddress((void**)&outx, g_outx);
    cudaGetSymbolAddress((void**)&sq,   g_sq);
    cudaGetSymbolAddress((void**)&embh, g_embh);
    cudaGetSymbolAddress((void**)&embl, g_embl);
    cudaGetSymbolAddress((void**)&xlh,  g_xlh);
    cudaGetSymbolAddress((void**)&xll,  g_xll);
    cudaGetSymbolAddress((void**)&degp, g_degp);
    cudaGetSymbolAddress((void**)&accp, g_accp);
    cudaGetSymbolAddress((void**)&cnt,  g_cnt);

    cudaFuncSetAttribute((const void*)adj_mma_kernel,
                         cudaFuncAttributeMaxDynamicSharedMemorySize,
                         ADJ_SMEM_BYTES);

    // out_x = relu(x@W0+b0) fp32; x_last = x@W2+b2 -> bf16 hi/lo planes
    gemm01_kernel<<<dim3(6, NN / 64), 256>>>(x, W0, b0, outx, W2, b2, xlh, xll);
    // emb = relu(out_x @ W1 + b1) -> bf16 hi/lo planes + row sq
    gemm_emb_kernel<<<dim3(1, NN / 32), 256>>>(outx, W1, b1, embh, embl, sq);
    // warp-MMA fused adjacency + deg + A@x_last + fused final reduction
    adj_mma_kernel<<<dim3(NN / IBLK, JSPLIT), 256, ADJ_SMEM_BYTES>>>(
        embh, embl, sq, xlh, xll, temp, theta, adj_out, degp, accp, out, cnt);
}

// round 13
// speedup vs baseline: 2.0874x; 2.0874x over previous
#include <cuda_runtime.h>
#include <cuda_bf16.h>
#include <cstdint>

#define NN 2048
#define DIN 128
#define HH 256
#define DE 64
#define JSPLIT 8
#define JTILE 64
#define TILES 4              // (NN / JSPLIT) / JTILE
#define IBLK 64

typedef unsigned long long u64;
typedef unsigned int u32;

__device__ float g_outx[NN * HH];
__device__ float g_sq[NN];
__device__ __align__(16) __nv_bfloat16 g_embh[NN * DE];
__device__ __align__(16) __nv_bfloat16 g_embl[NN * DE];
__device__ __align__(16) __nv_bfloat16 g_xlh[NN * DIN];
__device__ __align__(16) __nv_bfloat16 g_xll[NN * DIN];
__device__ float g_degp[JSPLIT * NN];
__device__ float g_accp[(size_t)JSPLIT * NN * DIN];

// ---- smem layout (bytes). pitches mod 128B == 16B -> ldmatrix conflict-free.
#define P1B 144u
#define P2B 272u
#define OF_EI_H 0u                    // 64 x P1B
#define OF_EI_L 9216u
#define OF_EJ_H 18432u                // 64 x P1B
#define OF_EJ_L 27648u
#define OF_XT_H 36864u                // 64 x P2B
#define OF_XT_L 54272u
#define OF_S_H  71680u                // 64 x P1B
#define OF_S_L  80896u
#define OF_SQJ  90112u                // 64 floats
#define OF_DEG  90368u                // 2 x 64 floats
#define ADJ_SMEM_BYTES 90880u

__device__ __forceinline__ u32 smem_u32(const void* p) {
    u32 a;
    asm("{ .reg .u64 t; cvta.to.shared.u64 t, %1; cvt.u32.u64 %0, t; }"
        : "=r"(a) : "l"(p));
    return a;
}
__device__ __forceinline__ void ldsm4(u32* r, u32 a) {
    asm volatile("ldmatrix.sync.aligned.m8n8.x4.shared.b16 {%0,%1,%2,%3}, [%4];"
        : "=r"(r[0]), "=r"(r[1]), "=r"(r[2]), "=r"(r[3]) : "r"(a));
}
__device__ __forceinline__ void ldsm4t(u32* r, u32 a) {
    asm volatile("ldmatrix.sync.aligned.m8n8.x4.trans.shared.b16 {%0,%1,%2,%3}, [%4];"
        : "=r"(r[0]), "=r"(r[1]), "=r"(r[2]), "=r"(r[3]) : "r"(a));
}
__device__ __forceinline__ void mma_bf16(float* c, const u32* a, u32 b0, u32 b1) {
    asm volatile(
        "mma.sync.aligned.m16n8k16.row.col.f32.bf16.bf16.f32 "
        "{%0,%1,%2,%3}, {%4,%5,%6,%7}, {%8,%9}, {%0,%1,%2,%3};"
        : "+f"(c[0]), "+f"(c[1]), "+f"(c[2]), "+f"(c[3])
        : "r"(a[0]), "r"(a[1]), "r"(a[2]), "r"(a[3]), "r"(b0), "r"(b1));
}
__device__ __forceinline__ float fast_rcp(float x) {
    float r = __uint_as_float(0x7EF311C3u - __float_as_uint(x));
    r = r * (2.0f - x * r);
    r = r * (2.0f - x * r);
    return r;
}
__device__ __forceinline__ void split_store(float2 v, char* smp, u32 off, u32 ldelta) {
    __nv_bfloat16 h0 = __float2bfloat16(v.x);
    __nv_bfloat16 h1 = __float2bfloat16(v.y);
    float l0 = v.x - __bfloat162float(h0);
    float l1 = v.y - __bfloat162float(h1);
    __nv_bfloat162 hp; hp.x = h0; hp.y = h1;
    __nv_bfloat162 lp; lp.x = __float2bfloat16(l0); lp.y = __float2bfloat16(l1);
    *(__nv_bfloat162*)(smp + off) = hp;
    *(__nv_bfloat162*)(smp + off + ldelta) = lp;
}
__device__ __forceinline__ void split_store_g(float v0, float v1,
                                              __nv_bfloat16* gh, __nv_bfloat16* gl) {
    __nv_bfloat16 h0 = __float2bfloat16(v0);
    __nv_bfloat16 h1 = __float2bfloat16(v1);
    float l0 = v0 - __bfloat162float(h0);
    float l1 = v1 - __bfloat162float(h1);
    __nv_bfloat162 hp; hp.x = h0; hp.y = h1;
    __nv_bfloat162 lp; lp.x = __float2bfloat16(l0); lp.y = __float2bfloat16(l1);
    *(__nv_bfloat162*)gh = hp;
    *(__nv_bfloat162*)gl = lp;
}

// ---------------------------------------------------------------------------
// Merged prologue GEMM on x (vectorized LDS.128 inner loop):
//   blocks 0..3 -> out_x = relu(x@W0+b0) fp32 [2048,256]
//   blocks 4..5 -> x_last = x@W2+b2 -> bf16 hi/lo planes xlh/xll [2048,128]
// smem pads = 68 floats (272B pitch == 16 mod 128 -> conflict-free float4).
// ---------------------------------------------------------------------------
__global__ void gemm01_kernel(const float* __restrict__ A,
                              const float* __restrict__ W0,
                              const float* __restrict__ b0,
                              float* __restrict__ outx,
                              const float* __restrict__ W2,
                              const float* __restrict__ b2,
                              __nv_bfloat16* __restrict__ xlh,
                              __nv_bfloat16* __restrict__ xll) {
    __shared__ float As[16][68];
    __shared__ float Bs[16][68];
    const bool second = blockIdx.x >= 4;
    const float* B = second ? W2 : W0;
    const float* bias = second ? b2 : b0;
    const int N = second ? DIN : HH;
    const int nbase = (second ? (blockIdx.x - 4) : blockIdx.x) * 64;

    int tid = threadIdx.x;
    int tx = tid & 15, ty = tid >> 4;
    int mbase = blockIdx.y * 64;

    float acc[4][4];
#pragma unroll
    for (int i = 0; i < 4; i++)
#pragma unroll
        for (int j = 0; j < 4; j++) acc[i][j] = 0.f;

#pragma unroll
    for (int k0 = 0; k0 < DIN; k0 += 16) {
        {   // A: 64 rows x 16 k -> transposed store (scatter STS, 4 per thread)
            int m = tid >> 2;
            int k = (tid & 3) << 2;
            float4 av = *reinterpret_cast<const float4*>(
                A + (size_t)(mbase + m) * DIN + k0 + k);
            As[k + 0][m] = av.x; As[k + 1][m] = av.y;
            As[k + 2][m] = av.z; As[k + 3][m] = av.w;
        }
        {   // B: 16 k x 64 n -> one LDG.128 + one STS.128 per thread
            int kk = tid >> 4;
            int n4 = (tid & 15) << 2;
            float4 bv = *reinterpret_cast<const float4*>(
                B + (size_t)(k0 + kk) * N + nbase + n4);
            *reinterpret_cast<float4*>(&Bs[kk][n4]) = bv;
        }
        __syncthreads();
#pragma unroll
        for (int kk = 0; kk < 16; kk++) {
            float4 a4 = *reinterpret_cast<const float4*>(&As[kk][ty * 4]);
            float4 b4 = *reinterpret_cast<const float4*>(&Bs[kk][tx * 4]);
            float a[4] = {a4.x, a4.y, a4.z, a4.w};
            float b[4] = {b4.x, b4.y, b4.z, b4.w};
#pragma unroll
            for (int i = 0; i < 4; i++)
#pragma unroll
                for (int j = 0; j < 4; j++) acc[i][j] += a[i] * b[j];
        }
        __syncthreads();
    }
#pragma unroll
    for (int i = 0; i < 4; i++) {
        int row = mbase + ty * 4 + i;
        if (!second) {
#pragma unroll
            for (int j = 0; j < 4; j++) {
                int col = nbase + tx * 4 + j;
                float v = acc[i][j] + bias[col];
                outx[(size_t)row * HH + col] = v > 0.f ? v : 0.f;
            }
        } else {
            int col = nbase + tx * 4;
            float v[4];
#pragma unroll
            for (int j = 0; j < 4; j++) v[j] = acc[i][j] + bias[col + j];
            split_store_g(v[0], v[1], &xlh[(size_t)row * DIN + col],
                          &xll[(size_t)row * DIN + col]);
            split_store_g(v[2], v[3], &xlh[(size_t)row * DIN + col + 2],
                          &xll[(size_t)row * DIN + col + 2]);
        }
    }
}

// ---------------------------------------------------------------------------
// emb GEMM: emb = relu(out_x @ W1 + b1) -> bf16 hi/lo planes + fused row-sq.
// BM=32 (grid 64 CTAs); thread tile 2x4; vectorized inner loads.
// ---------------------------------------------------------------------------
__global__ void gemm_emb_kernel(const float* __restrict__ A,
                                const float* __restrict__ B,
                                const float* __restrict__ bias,
                                __nv_bfloat16* __restrict__ embh,
                                __nv_bfloat16* __restrict__ embl,
                                float* __restrict__ sqout) {
    __shared__ float As[16][36];
    __shared__ float Bs[16][68];
    const int N = DE, K = HH;
    int tid = threadIdx.x;
    int tx = tid & 15, ty = tid >> 4;
    int mbase = blockIdx.y * 32;

    float acc[2][4];
#pragma unroll
    for (int i = 0; i < 2; i++)
#pragma unroll
        for (int j = 0; j < 4; j++) acc[i][j] = 0.f;

#pragma unroll 4
    for (int k0 = 0; k0 < K; k0 += 16) {
        {
            int m = tid >> 3;
            int k = (tid & 7) << 1;
            float2 av = *reinterpret_cast<const float2*>(
                A + (size_t)(mbase + m) * K + k0 + k);
            As[k + 0][m] = av.x; As[k + 1][m] = av.y;
        }
        if (tid < 256) {
            int kk = tid >> 4;
            int n4 = (tid & 15) << 2;
            if (n4 < N) {
                float4 bv = *reinterpret_cast<const float4*>(
                    B + (size_t)(k0 + kk) * N + n4);
                *reinterpret_cast<float4*>(&Bs[kk][n4]) = bv;
            }
        }
        __syncthreads();
#pragma unroll
        for (int kk = 0; kk < 16; kk++) {
            float a[2], b[4];
            a[0] = As[kk][ty * 2];
            a[1] = As[kk][ty * 2 + 1];
            float4 b4 = *reinterpret_cast<const float4*>(&Bs[kk][tx * 4]);
            b[0] = b4.x; b[1] = b4.y; b[2] = b4.z; b[3] = b4.w;
#pragma unroll
            for (int i = 0; i < 2; i++)
#pragma unroll
                for (int j = 0; j < 4; j++) acc[i][j] += a[i] * b[j];
        }
        __syncthreads();
    }

    float rowsq[2] = {0.f, 0.f};
#pragma unroll
    for (int i = 0; i < 2; i++) {
        int row = mbase + ty * 2 + i;
        int col = tx * 4;
        float v[4];
#pragma unroll
        for (int j = 0; j < 4; j++) {
            float u = acc[i][j] + bias[col + j];
            u = u > 0.f ? u : 0.f;
            v[j] = u;
            rowsq[i] += u * u;
        }
        split_store_g(v[0], v[1], &embh[(size_t)row * DE + col],
                      &embl[(size_t)row * DE + col]);
        split_store_g(v[2], v[3], &embh[(size_t)row * DE + col + 2],
                      &embl[(size_t)row * DE + col + 2]);
    }
    __shared__ float sqred[32][17];
#pragma unroll
    for (int i = 0; i < 2; i++) sqred[ty * 2 + i][tx] = rowsq[i];
    __syncthreads();
    if (tid < 32) {
        float s = 0.f;
#pragma unroll
        for (int j = 0; j < 16; j++) s += sqred[tid][j];
        sqout[mbase + tid] = s;
    }
}

// ---------------------------------------------------------------------------
// Warp-MMA fused adjacency kernel (bf16-split, 3-MMA compensation).
// CTA = 64 i-rows x one j-split (4 tiles of 64 j). 256 threads (8 warps).
// 2 CTAs/SM. (Proven R8 body.)
// ---------------------------------------------------------------------------
__global__ __launch_bounds__(256, 2)
void adj_mma_kernel(const __nv_bfloat16* __restrict__ embh,
                    const __nv_bfloat16* __restrict__ embl,
                    const float* __restrict__ sq,
                    const __nv_bfloat16* __restrict__ xlh,
                    const __nv_bfloat16* __restrict__ xll,
                    const float* __restrict__ temp_p,
                    const float* __restrict__ theta_p,
                    float* __restrict__ adj_out,
                    float* __restrict__ degp, float* __restrict__ accp) {
    extern __shared__ char sm[];
    const u32 sb = smem_u32(sm);
    float* sqjc  = (float*)(sm + OF_SQJ);
    float* degsm = (float*)(sm + OF_DEG);

    const int t = threadIdx.x;
    const int wm = t >> 5;
    const int lane = t & 31;
    const int wg = wm >> 2;
    const int wr = wm & 3;
    const int i0 = blockIdx.x * IBLK;
    const int jsp = blockIdx.y;
    const int jbase = jsp * (TILES * JTILE);
    const float cA = 1.0f + *temp_p;
    const float cB = 5.0f + *theta_p;
    const float c2A = 2.0f * cA;

    // ---- stage EI planes ----
    {
        const uint4* sH = (const uint4*)embh + (size_t)i0 * 8;
        const uint4* sL = (const uint4*)embl + (size_t)i0 * 8;
        for (int idx = t; idx < 512; idx += 256) {
            int row = idx >> 3, q = idx & 7;
            *(uint4*)(sm + OF_EI_H + row * P1B + q * 16) = sH[row * 8 + q];
            *(uint4*)(sm + OF_EI_L + row * P1B + q * 16) = sL[row * 8 + q];
        }
    }
    __syncthreads();

    // ---- A fragments (tile-invariant, hoisted) ----
    u32 ah[4][4], al[4][4];
    {
        const u32 abase = sb + OF_EI_H + (wr * 16 + (lane & 15)) * P1B + (lane >> 4) * 16;
#pragma unroll
        for (int ks = 0; ks < 4; ks++) {
            ldsm4(ah[ks], abase + ks * 32);
            ldsm4(al[ks], abase + (OF_EI_L - OF_EI_H) + ks * 32);
        }
    }

    const int ra = wr * 16 + (lane >> 2);
    const int rb = ra + 8;
    const float cbi_a = cB - cA * sq[i0 + ra];
    const float cbi_b = cB - cA * sq[i0 + rb];

    float acc2[8][4];
#pragma unroll
    for (int n = 0; n < 8; n++)
#pragma unroll
        for (int q = 0; q < 4; q++) acc2[n][q] = 0.f;
    float dega = 0.f, degb = 0.f;

    for (int tt = 0; tt < TILES; ++tt) {
        const int jb = jbase + tt * JTILE;
        if (tt > 0) __syncthreads();

        {
            const uint4* sH = (const uint4*)embh + (size_t)jb * 8;
            const uint4* sL = (const uint4*)embl + (size_t)jb * 8;
            for (int idx = t; idx < 512; idx += 256) {
                int row = idx >> 3, q = idx & 7;
                *(uint4*)(sm + OF_EJ_H + row * P1B + q * 16) = sH[row * 8 + q];
                *(uint4*)(sm + OF_EJ_L + row * P1B + q * 16) = sL[row * 8 + q];
            }
        }
        {
            const uint4* sH = (const uint4*)xlh + (size_t)jb * 16;
            const uint4* sL = (const uint4*)xll + (size_t)jb * 16;
            for (int idx = t; idx < 1024; idx += 256) {
                int row = idx >> 4, q = idx & 15;
                *(uint4*)(sm + OF_XT_H + row * P2B + q * 16) = sH[row * 16 + q];
                *(uint4*)(sm + OF_XT_L + row * P2B + q * 16) = sL[row * 16 + q];
            }
        }
        if (t < JTILE) sqjc[t] = cA * sq[jb + t];
        __syncthreads();

        // ---- phase 1: dot = embi @ embj^T ----
        float acc1[4][4];
#pragma unroll
        for (int n = 0; n < 4; n++)
#pragma unroll
            for (int q = 0; q < 4; q++) acc1[n][q] = 0.f;

        const u32 bjbase = sb + OF_EJ_H
                           + (wg * 32 + (lane & 7) + (lane >> 4) * 8) * P1B
                           + ((lane >> 3) & 1) * 16;
#pragma unroll
        for (int np = 0; np < 2; np++) {
#pragma unroll
            for (int ks = 0; ks < 4; ks++) {
                u32 bh[4], bl[4];
                u32 ba = bjbase + np * 16 * P1B + ks * 32;
                ldsm4(bh, ba);
                ldsm4(bl, ba + (OF_EJ_L - OF_EJ_H));
                mma_bf16(acc1[np * 2],     ah[ks], bh[0], bh[1]);
                mma_bf16(acc1[np * 2],     ah[ks], bl[0], bl[1]);
                mma_bf16(acc1[np * 2],     al[ks], bh[0], bh[1]);
                mma_bf16(acc1[np * 2 + 1], ah[ks], bh[2], bh[3]);
                mma_bf16(acc1[np * 2 + 1], ah[ks], bl[2], bl[3]);
                mma_bf16(acc1[np * 2 + 1], al[ks], bh[2], bh[3]);
            }
        }

        // ---- epilogue: sigmoid + eye, adj STG, deg, S split -> smem ----
#pragma unroll
        for (int nt = 0; nt < 4; nt++) {
            int jc = wg * 32 + nt * 8 + 2 * (lane & 3);
            float sj0 = sqjc[jc], sj1 = sqjc[jc + 1];
            float z00 = fmaf(c2A, acc1[nt][0], cbi_a - sj0);
            float z01 = fmaf(c2A, acc1[nt][1], cbi_a - sj1);
            float z10 = fmaf(c2A, acc1[nt][2], cbi_b - sj0);
            float z11 = fmaf(c2A, acc1[nt][3], cbi_b - sj1);
            float p00 = fast_rcp(1.f + __expf(-z00));
            float p01 = fast_rcp(1.f + __expf(-z01));
            float p10 = fast_rcp(1.f + __expf(-z10));
            float p11 = fast_rcp(1.f + __expf(-z11));
            if (i0 + ra == jb + jc)     p00 += 1.f;
            if (i0 + ra == jb + jc + 1) p01 += 1.f;
            if (i0 + rb == jb + jc)     p10 += 1.f;
            if (i0 + rb == jb + jc + 1) p11 += 1.f;
            dega += p00 + p01;
            degb += p10 + p11;
            *(float2*)&adj_out[(size_t)(i0 + ra) * NN + jb + jc] = make_float2(p00, p01);
            *(float2*)&adj_out[(size_t)(i0 + rb) * NN + jb + jc] = make_float2(p10, p11);
            split_store(make_float2(p00, p01), sm + OF_S_H,
                        ra * P1B + jc * 2, OF_S_L - OF_S_H);
            split_store(make_float2(p10, p11), sm + OF_S_H,
                        rb * P1B + jc * 2, OF_S_L - OF_S_H);
        }
        __syncthreads();

        // ---- phase 2: acc2 += S @ XT^T ----
        const u32 sbase = sb + OF_S_H + (wr * 16 + (lane & 15)) * P1B + (lane >> 4) * 16;
        const u32 btbase = sb + OF_XT_H
                           + ((lane & 7) + ((lane >> 3) & 1) * 8) * P2B
                           + wg * 128 + (lane >> 4) * 16;
#pragma unroll
        for (int ks = 0; ks < 4; ks++) {
            u32 sh[4], sl[4];
            ldsm4(sh, sbase + ks * 32);
            ldsm4(sl, sbase + (OF_S_L - OF_S_H) + ks * 32);
#pragma unroll
            for (int ndp = 0; ndp < 4; ndp++) {
                u32 bh[4], bl[4];
                u32 ba = btbase + ks * 16 * P2B + ndp * 32;
                ldsm4t(bh, ba);
                ldsm4t(bl, ba + (OF_XT_L - OF_XT_H));
                mma_bf16(acc2[ndp * 2],     sh, bh[0], bh[1]);
                mma_bf16(acc2[ndp * 2],     sh, bl[0], bl[1]);
                mma_bf16(acc2[ndp * 2],     sl, bh[0], bh[1]);
                mma_bf16(acc2[ndp * 2 + 1], sh, bh[2], bh[3]);
                mma_bf16(acc2[ndp * 2 + 1], sh, bl[2], bl[3]);
                mma_bf16(acc2[ndp * 2 + 1], sl, bh[2], bh[3]);
            }
        }
    }

    // ---- deg reduction into degp ----
    dega += __shfl_xor_sync(0xffffffffu, dega, 1);
    dega += __shfl_xor_sync(0xffffffffu, dega, 2);
    degb += __shfl_xor_sync(0xffffffffu, degb, 1);
    degb += __shfl_xor_sync(0xffffffffu, degb, 2);
    if ((lane & 3) == 0) {
        degsm[wg * IBLK + ra] = dega;
        degsm[wg * IBLK + rb] = degb;
    }
    __syncthreads();
    if (t < IBLK)
        degp[jsp * NN + i0 + t] = degsm[t] + degsm[IBLK + t];

    // ---- write acc2 partials ----
    float* ap = accp + ((size_t)jsp * NN + i0) * DIN;
#pragma unroll
    for (int nt = 0; nt < 8; nt++) {
        int dc = wg * 64 + nt * 8 + 2 * (lane & 3);
        *(float2*)&ap[(size_t)ra * DIN + dc] = make_float2(acc2[nt][0], acc2[nt][1]);
        *(float2*)&ap[(size_t)rb * DIN + dc] = make_float2(acc2[nt][2], acc2[nt][3]);
    }
}

// ---------------------------------------------------------------------------
// Reduce j-split partials: out = relu((sum acc) / (sum deg)).  float4 lanes.
// ---------------------------------------------------------------------------
__global__ void finalize_kernel(const float* __restrict__ accp,
                                const float* __restrict__ degp,
                                float* __restrict__ out) {
    __shared__ float ds[8];
    const int t = threadIdx.x;
    const int base4 = blockIdx.x * 256;
    if (t < 8) {
        int row = blockIdx.x * 8 + t;
        float d = 0.f;
#pragma unroll
        for (int k = 0; k < JSPLIT; k++) d += degp[k * NN + row];
        ds[t] = d;
    }
    __syncthreads();
    const int idx4 = base4 + t;
    const float4* apv = (const float4*)accp;
    float4 a = apv[idx4];
#pragma unroll
    for (int k = 1; k < JSPLIT; k++) {
        float4 b = apv[(size_t)k * (NN * DIN / 4) + idx4];
        a.x += b.x; a.y += b.y; a.z += b.z; a.w += b.w;
    }
    float dinv = 1.0f / ds[t >> 5];
    float4 v;
    v.x = a.x * dinv; v.y = a.y * dinv; v.z = a.z * dinv; v.w = a.w * dinv;
    v.x = v.x > 0.f ? v.x : 0.f;  v.y = v.y > 0.f ? v.y : 0.f;
    v.z = v.z > 0.f ? v.z : 0.f;  v.w = v.w > 0.f ? v.w : 0.f;
    ((float4*)out)[idx4] = v;
}

extern "C" void kernel_launch(void* const* d_in, const int* in_sizes, int n_in,
                              void* d_out, int out_size) {
    const float* x     = (const float*)d_in[0];
    const float* W0    = (const float*)d_in[2];
    const float* b0    = (const float*)d_in[3];
    const float* W1    = (const float*)d_in[4];
    const float* b1    = (const float*)d_in[5];
    const float* W2    = (const float*)d_in[6];
    const float* b2    = (const float*)d_in[7];
    const float* temp  = (const float*)d_in[8];
    const float* theta = (const float*)d_in[9];

    float* out = (float*)d_out;                 // [NN, DIN] first
    float* adj_out = out + (size_t)NN * DIN;    // then [NN*NN] adjacency

    float *outx, *sq, *degp, *accp;
    __nv_bfloat16 *embh, *embl, *xlh, *xll;
    cudaGetSymbolAddress((void**)&outx, g_outx);
    cudaGetSymbolAddress((void**)&sq,   g_sq);
    cudaGetSymbolAddress((void**)&embh, g_embh);
    cudaGetSymbolAddress((void**)&embl, g_embl);
    cudaGetSymbolAddress((void**)&xlh,  g_xlh);
    cudaGetSymbolAddress((void**)&xll,  g_xll);
    cudaGetSymbolAddress((void**)&degp, g_degp);
    cudaGetSymbolAddress((void**)&accp, g_accp);

    cudaFuncSetAttribute((const void*)adj_mma_kernel,
                         cudaFuncAttributeMaxDynamicSharedMemorySize,
                         ADJ_SMEM_BYTES);

    // out_x = relu(x@W0+b0) fp32; x_last = x@W2+b2 -> bf16 hi/lo planes
    gemm01_kernel<<<dim3(6, NN / 64), 256>>>(x, W0, b0, outx, W2, b2, xlh, xll);
    // emb = relu(out_x @ W1 + b1) -> bf16 hi/lo planes + row sq
    gemm_emb_kernel<<<dim3(1, NN / 32), 256>>>(outx, W1, b1, embh, embl, sq);
    // warp-MMA fused adjacency + deg + partial A@x_last
    adj_mma_kernel<<<dim3(NN / IBLK, JSPLIT), 256, ADJ_SMEM_BYTES>>>(
        embh, embl, sq, xlh, xll, temp, theta, adj_out, degp, accp);
    // out = relu((A @ x_last) / deg)
    finalize_kernel<<<(NN * DIN / 4) / 256, 256>>>(accp, degp, out);
}